// round 1
// baseline (speedup 1.0000x reference)
#include <cuda_runtime.h>
#include <cstdint>

// Problem constants (fixed by the dataset): x:(8,4096,2048) f32, weights:(4,2048,2048),
// biases:(4,2048), perms:(3,4096) i32. out:(8,4096,2048) f32.
#define HDIM   2048
#define SEQ    4096
#define NBATCH 8
#define MTOT   (NBATCH * SEQ)   // 32768

// 256 MB ping-pong scratch (device global: allocation-guard-safe).
__device__ float g_scratch[(size_t)MTOT * HDIM];

// C[r, o] = sum_h A[gather(r), h] * W[o, h] + bias[o]
// gather(r): r -> b*SEQ + perm[s]  (b = r/SEQ, s = r%SEQ), identity if perm==nullptr.
// Tile: BM=128, BN=128, BK=16; 256 threads; 8x8 accumulators per thread.
__global__ __launch_bounds__(256)
void gemm_bias_perm(const float* __restrict__ A,
                    const float* __restrict__ W,
                    const float* __restrict__ bias,
                    const int*   __restrict__ perm,
                    float*       __restrict__ C)
{
    // Padded to 132 floats: keeps 16B alignment (132*4 % 16 == 0) and reduces
    // STS bank conflicts of the transposing store.
    __shared__ float As[16][132];
    __shared__ float Bs[16][132];

    const int tid = threadIdx.x;
    const int m0  = blockIdx.y * 128;
    const int n0  = blockIdx.x * 128;

    // gmem tile-load mapping: thread covers rows lr0 and lr0+64, 4 contiguous k (cg).
    const int lr0 = tid >> 2;          // 0..63
    const int lr1 = lr0 + 64;
    const int cg  = (tid & 3) * 4;     // 0,4,8,12

    // A row gather (fused permutation). perm is shared across batch.
    const int gr0 = m0 + lr0;
    const int gr1 = m0 + lr1;
    int src0, src1;
    if (perm) {
        src0 = (gr0 & ~(SEQ - 1)) + perm[gr0 & (SEQ - 1)];
        src1 = (gr1 & ~(SEQ - 1)) + perm[gr1 & (SEQ - 1)];
    } else {
        src0 = gr0;
        src1 = gr1;
    }
    const float* arow0 = A + (size_t)src0 * HDIM;
    const float* arow1 = A + (size_t)src1 * HDIM;
    const float* wrow0 = W + (size_t)(n0 + lr0) * HDIM;
    const float* wrow1 = W + (size_t)(n0 + lr1) * HDIM;

    // compute mapping: 16x16 thread grid, 8x8 outputs each.
    const int tm = (tid >> 4) * 8;
    const int tn = (tid & 15) * 8;

    float acc[8][8];
#pragma unroll
    for (int i = 0; i < 8; ++i)
#pragma unroll
        for (int j = 0; j < 8; ++j) acc[i][j] = 0.0f;

    for (int k0 = 0; k0 < HDIM; k0 += 16) {
        const float4 a0 = *(const float4*)(arow0 + k0 + cg);
        const float4 a1 = *(const float4*)(arow1 + k0 + cg);
        const float4 w0 = *(const float4*)(wrow0 + k0 + cg);
        const float4 w1 = *(const float4*)(wrow1 + k0 + cg);

        __syncthreads();   // previous iteration's reads done before overwrite

        As[cg + 0][lr0] = a0.x; As[cg + 1][lr0] = a0.y;
        As[cg + 2][lr0] = a0.z; As[cg + 3][lr0] = a0.w;
        As[cg + 0][lr1] = a1.x; As[cg + 1][lr1] = a1.y;
        As[cg + 2][lr1] = a1.z; As[cg + 3][lr1] = a1.w;

        Bs[cg + 0][lr0] = w0.x; Bs[cg + 1][lr0] = w0.y;
        Bs[cg + 2][lr0] = w0.z; Bs[cg + 3][lr0] = w0.w;
        Bs[cg + 0][lr1] = w1.x; Bs[cg + 1][lr1] = w1.y;
        Bs[cg + 2][lr1] = w1.z; Bs[cg + 3][lr1] = w1.w;

        __syncthreads();

#pragma unroll
        for (int k = 0; k < 16; ++k) {
            float av[8], bv[8];
            *(float4*)&av[0] = *(const float4*)&As[k][tm];
            *(float4*)&av[4] = *(const float4*)&As[k][tm + 4];
            *(float4*)&bv[0] = *(const float4*)&Bs[k][tn];
            *(float4*)&bv[4] = *(const float4*)&Bs[k][tn + 4];
#pragma unroll
            for (int i = 0; i < 8; ++i)
#pragma unroll
                for (int j = 0; j < 8; ++j)
                    acc[i][j] = fmaf(av[i], bv[j], acc[i][j]);
        }
    }

    // Epilogue: bias add + vectorized store.
    float bb[8];
#pragma unroll
    for (int j = 0; j < 8; ++j) bb[j] = bias[n0 + tn + j];

#pragma unroll
    for (int i = 0; i < 8; ++i) {
        const size_t off = (size_t)(m0 + tm + i) * HDIM + n0 + tn;
        float4 o0, o1;
        o0.x = acc[i][0] + bb[0]; o0.y = acc[i][1] + bb[1];
        o0.z = acc[i][2] + bb[2]; o0.w = acc[i][3] + bb[3];
        o1.x = acc[i][4] + bb[4]; o1.y = acc[i][5] + bb[5];
        o1.z = acc[i][6] + bb[6]; o1.w = acc[i][7] + bb[7];
        *(float4*)(C + off)     = o0;
        *(float4*)(C + off + 4) = o1;
    }
}

extern "C" void kernel_launch(void* const* d_in, const int* in_sizes, int n_in,
                              void* d_out, int out_size)
{
    const float* x       = (const float*)d_in[0];
    const float* weights = (const float*)d_in[1];
    const float* biases  = (const float*)d_in[2];
    const int*   perms   = (const int*)  d_in[3];
    float*       out     = (float*)d_out;

    float* scratch = nullptr;
    cudaGetSymbolAddress((void**)&scratch, g_scratch);   // query only; capture-safe

    const dim3 grid(HDIM / 128, MTOT / 128);   // (16, 256)
    const dim3 block(256);
    const size_t WSTRIDE = (size_t)HDIM * HDIM;

    // Layer 0: x -> scratch (no perm)
    gemm_bias_perm<<<grid, block>>>(x, weights, biases, nullptr, scratch);
    // Layer 1: scratch -> out, gather by perms[0]
    gemm_bias_perm<<<grid, block>>>(scratch, weights + WSTRIDE, biases + HDIM,
                                    perms, out);
    // Layer 2: out -> scratch, gather by perms[1]
    gemm_bias_perm<<<grid, block>>>(out, weights + 2 * WSTRIDE, biases + 2 * HDIM,
                                    perms + SEQ, scratch);
    // Layer 3: scratch -> out, gather by perms[2]
    gemm_bias_perm<<<grid, block>>>(scratch, weights + 3 * WSTRIDE, biases + 3 * HDIM,
                                    perms + 2 * SEQ, out);
}

// round 8
// speedup vs baseline: 3.3277x; 3.3277x over previous
#include <cuda_runtime.h>
#include <cuda_bf16.h>
#include <cuda.h>
#include <cstdint>

// ---------------- problem constants ----------------
#define HDIM   2048
#define SEQ    4096
#define NBATCH 8
#define MTOT   (NBATCH * SEQ)       // 32768
#define NLAYER 4

// ---------------- GEMM tile config ----------------
#define BM 256
#define BN 128
#define BK 64                        // 64 bf16 = 128 B rows (SW128)
#define KCHUNKS (HDIM / BK)          // 32
#define NSTAGES 2

// smem layout (bytes)
#define OFF_FULL(s)  ((s) * 8)
#define OFF_BIAS     64              // BN floats = 512 B
#define OFF_STAGE    1024            // 1024-aligned for swizzle
#define OFF_AHI      0               // 256*128 = 32768
#define OFF_ALO      32768
#define OFF_BHI      65536           // 128*128 = 16384
#define OFF_BLO      81920
#define STAGE_BYTES  98304
#define SMEM_TOTAL   (OFF_STAGE + NSTAGES * STAGE_BYTES)   // 197632

// ---------------- device scratch ----------------
__device__ __align__(1024) __nv_bfloat16 g_ahi[2ull * MTOT * HDIM];
__device__ __align__(1024) __nv_bfloat16 g_alo[2ull * MTOT * HDIM];
__device__ __align__(1024) __nv_bfloat16 g_whi[(size_t)NLAYER * HDIM * HDIM];
__device__ __align__(1024) __nv_bfloat16 g_wlo[(size_t)NLAYER * HDIM * HDIM];
__device__ int g_inv[(NLAYER - 1) * SEQ];

// ---------------- PTX helpers (baseline sm_103 only; NO 'a' features) ----------------
__device__ __forceinline__ uint32_t smem_u32(const void* p) {
    return (uint32_t)__cvta_generic_to_shared(p);
}

#define MBARRIER_INIT(addr, cnt) \
    asm volatile("mbarrier.init.shared.b64 [%0], %1;" :: "r"(addr), "r"(cnt) : "memory")

#define MBARRIER_EXPECT_TX(addr, bytes) \
    asm volatile("mbarrier.arrive.expect_tx.shared.b64 _, [%0], %1;" :: "r"(addr), "r"(bytes) : "memory")

#define MBARRIER_WAIT_PARITY(mbar_smem_addr, phase_parity) do { \
    uint32_t _mbar = (uint32_t)(mbar_smem_addr); \
    uint32_t _parity = (uint32_t)(phase_parity); \
    uint32_t _done_; \
    asm volatile( \
        "{\n\t.reg .pred p;\n\t" \
        "mbarrier.try_wait.parity.acquire.cta.shared::cta.b64 p, [%1], %2;\n\t" \
        "selp.b32 %0, 1, 0, p;\n\t}" \
        : "=r"(_done_) : "r"(_mbar), "r"(_parity) : "memory"); \
    if (!_done_) { \
        asm volatile( \
            "{\n\t.reg .pred P1;\n\t" \
            "WAIT_LOOP_%=:\n\t" \
            "mbarrier.try_wait.parity.acquire.cta.shared::cta.b64 P1, [%0], %1, 0x989680;\n\t" \
            "@P1 bra.uni WAIT_DONE_%=;\n\t" \
            "bra.uni WAIT_LOOP_%=;\n\t" \
            "WAIT_DONE_%=:\n\t}" \
            :: "r"(_mbar), "r"(_parity) : "memory"); \
    } \
} while (0)

#define TMA_LOAD_2D(dst, map, cx, cy, mbar) \
    asm volatile( \
        "cp.async.bulk.tensor.2d.shared::cta.global.tile.mbarrier::complete_tx::bytes " \
        "[%0], [%1, {%2, %3}], [%4];" \
        :: "r"((uint32_t)(dst)), "l"(map), "r"((int)(cx)), "r"((int)(cy)), "r"((uint32_t)(mbar)) \
        : "memory")

__device__ __forceinline__ void ldsm_x4(uint32_t* r, uint32_t addr) {
    asm volatile("ldmatrix.sync.aligned.m8n8.x4.shared.b16 {%0,%1,%2,%3}, [%4];"
        : "=r"(r[0]), "=r"(r[1]), "=r"(r[2]), "=r"(r[3]) : "r"(addr));
}

// D += A * B  (bf16 in, fp32 acc), m16n8k16
__device__ __forceinline__ void mma16816(float* d, const uint32_t* a, const uint32_t* b) {
    asm volatile("mma.sync.aligned.m16n8k16.row.col.f32.bf16.bf16.f32 "
        "{%0,%1,%2,%3}, {%4,%5,%6,%7}, {%8,%9}, {%0,%1,%2,%3};"
        : "+f"(d[0]), "+f"(d[1]), "+f"(d[2]), "+f"(d[3])
        : "r"(a[0]), "r"(a[1]), "r"(a[2]), "r"(a[3]), "r"(b[0]), "r"(b[1]));
}

// split fp32 -> (hi, lo) bf16
__device__ __forceinline__ void split1(float a, __nv_bfloat16& h, __nv_bfloat16& l) {
    h = __float2bfloat16(a);
    l = __float2bfloat16(a - __bfloat162float(h));
}

// ---------------- pre-kernels ----------------
__global__ void split_kernel(const float* __restrict__ in,
                             __nv_bfloat16* __restrict__ hi,
                             __nv_bfloat16* __restrict__ lo, int n4) {
    int stride = gridDim.x * blockDim.x;
    for (int i = blockIdx.x * blockDim.x + threadIdx.x; i < n4; i += stride) {
        float4 f = ((const float4*)in)[i];
        __nv_bfloat16 h0, h1, h2, h3, l0, l1, l2, l3;
        split1(f.x, h0, l0); split1(f.y, h1, l1);
        split1(f.z, h2, l2); split1(f.w, h3, l3);
        uint32_t ph0 = (uint32_t)__bfloat16_as_ushort(h0) | ((uint32_t)__bfloat16_as_ushort(h1) << 16);
        uint32_t ph1 = (uint32_t)__bfloat16_as_ushort(h2) | ((uint32_t)__bfloat16_as_ushort(h3) << 16);
        uint32_t pl0 = (uint32_t)__bfloat16_as_ushort(l0) | ((uint32_t)__bfloat16_as_ushort(l1) << 16);
        uint32_t pl1 = (uint32_t)__bfloat16_as_ushort(l2) | ((uint32_t)__bfloat16_as_ushort(l3) << 16);
        ((uint2*)hi)[i] = make_uint2(ph0, ph1);
        ((uint2*)lo)[i] = make_uint2(pl0, pl1);
    }
}

__global__ void invperm_kernel(const int* __restrict__ perms, int* __restrict__ inv) {
    int i = blockIdx.x * blockDim.x + threadIdx.x;
    if (i < (NLAYER - 1) * SEQ) {
        int l = i / SEQ, s = i % SEQ;
        inv[l * SEQ + perms[i]] = s;
    }
}

// ---------------- main GEMM layer kernel (Ampere-style HMMA) ----------------
// C[BM x BN] = sum_K (Ahi+Alo).(Bhi+Blo)^T via 3 terms; +bias; scatter by invperm.
__global__ void __launch_bounds__(256, 1)
gemm_layer(const __grid_constant__ CUtensorMap mapAhi,
           const __grid_constant__ CUtensorMap mapAlo,
           const __grid_constant__ CUtensorMap mapBhi,
           const __grid_constant__ CUtensorMap mapBlo,
           const float* __restrict__ bias,
           const int* __restrict__ invperm,
           __nv_bfloat16* __restrict__ outHi,
           __nv_bfloat16* __restrict__ outLo,
           float* __restrict__ outF)
{
    extern __shared__ char smem[];
    const uint32_t sb = smem_u32(smem);
    const int tid  = threadIdx.x;
    const int wid  = tid >> 5;
    const int lane = tid & 31;
    const int warp_m = wid & 3;       // 4 warps along M (64 rows each)
    const int warp_n = wid >> 2;      // 2 warps along N (64 cols each)
    const int m0 = blockIdx.y * BM;
    const int n0 = blockIdx.x * BN;

    float* bias_s = (float*)(smem + OFF_BIAS);
    for (int i = tid; i < BN; i += 256) bias_s[i] = bias[n0 + i];

    if (tid == 0) {
        MBARRIER_INIT(sb + OFF_FULL(0), 1);
        MBARRIER_INIT(sb + OFF_FULL(1), 1);
    }
    __syncthreads();

    if (tid == 0) {
#pragma unroll
        for (int c = 0; c < NSTAGES; ++c) {
            MBARRIER_EXPECT_TX(sb + OFF_FULL(c), STAGE_BYTES);
            const uint32_t base = sb + OFF_STAGE + c * STAGE_BYTES;
            const int k0 = c * BK;
            TMA_LOAD_2D(base + OFF_AHI, &mapAhi, k0, m0, sb + OFF_FULL(c));
            TMA_LOAD_2D(base + OFF_ALO, &mapAlo, k0, m0, sb + OFF_FULL(c));
            TMA_LOAD_2D(base + OFF_BHI, &mapBhi, k0, n0, sb + OFF_FULL(c));
            TMA_LOAD_2D(base + OFF_BLO, &mapBlo, k0, n0, sb + OFF_FULL(c));
        }
    }

    // per-lane ldmatrix geometry (SW128, 128B rows: phys_k = k ^ ((row&7)*16))
    const int rin = lane & 7;
    const int t8  = lane >> 3;                 // 8x8 tile index 0..3
    const int a_row_local = ((t8 & 1) << 3) + rin;   // A: tiles 0/1 rows, 2/3 k+16
    const int a_kadd      = (t8 >> 1) << 4;
    const int b_row_local = ((t8 >> 1) << 3) + rin;  // B: tiles 0/1 k, 2/3 n+8
    const int b_kadd      = (t8 & 1) << 4;
    const uint32_t ksw    = (uint32_t)(rin << 4);

    float acc[4][8][4];
#pragma unroll
    for (int i = 0; i < 4; ++i)
#pragma unroll
        for (int j = 0; j < 8; ++j)
#pragma unroll
            for (int k = 0; k < 4; ++k) acc[i][j][k] = 0.0f;

    for (int c = 0; c < KCHUNKS; ++c) {
        const int st = c & 1;
        MBARRIER_WAIT_PARITY(sb + OFF_FULL(st), (c >> 1) & 1);
        const uint32_t base = sb + OFF_STAGE + st * STAGE_BYTES;

#pragma unroll
        for (int kk = 0; kk < BK / 16; ++kk) {
            uint32_t ahi[4][4], alo[4][4];
#pragma unroll
            for (int mt = 0; mt < 4; ++mt) {
                const int row = warp_m * 64 + mt * 16 + a_row_local;
                const uint32_t koff = (uint32_t)(kk * 32 + a_kadd) ^ ksw;
                const uint32_t addr = base + OFF_AHI + row * 128 + koff;
                ldsm_x4(ahi[mt], addr);
                ldsm_x4(alo[mt], addr + (OFF_ALO - OFF_AHI));
            }
#pragma unroll
            for (int g = 0; g < 4; ++g) {
                const int rowb = warp_n * 64 + g * 16 + b_row_local;
                const uint32_t koff = (uint32_t)(kk * 32 + b_kadd) ^ ksw;
                const uint32_t baddr = base + OFF_BHI + rowb * 128 + koff;
                uint32_t bh[4], bl[4];
                ldsm_x4(bh, baddr);
                ldsm_x4(bl, baddr + (OFF_BLO - OFF_BHI));
#pragma unroll
                for (int mt = 0; mt < 4; ++mt) {
                    mma16816(acc[mt][2 * g],     ahi[mt], bh);       // hi*hi (n even)
                    mma16816(acc[mt][2 * g],     ahi[mt], bl);       // hi*lo
                    mma16816(acc[mt][2 * g],     alo[mt], bh);       // lo*hi
                    mma16816(acc[mt][2 * g + 1], ahi[mt], bh + 2);   // n odd
                    mma16816(acc[mt][2 * g + 1], ahi[mt], bl + 2);
                    mma16816(acc[mt][2 * g + 1], alo[mt], bh + 2);
                }
            }
        }
        __syncthreads();           // all warps done with stage st before refill
        if (tid == 0 && c + NSTAGES < KCHUNKS) {
            MBARRIER_EXPECT_TX(sb + OFF_FULL(st), STAGE_BYTES);
            const int k0 = (c + NSTAGES) * BK;
            TMA_LOAD_2D(base + OFF_AHI, &mapAhi, k0, m0, sb + OFF_FULL(st));
            TMA_LOAD_2D(base + OFF_ALO, &mapAlo, k0, m0, sb + OFF_FULL(st));
            TMA_LOAD_2D(base + OFF_BHI, &mapBhi, k0, n0, sb + OFF_FULL(st));
            TMA_LOAD_2D(base + OFF_BLO, &mapBlo, k0, n0, sb + OFF_FULL(st));
        }
    }

    // ---------------- epilogue: bias + (scatter-split | fp32 store) ----------------
#pragma unroll
    for (int mt = 0; mt < 4; ++mt) {
        const int r0 = m0 + warp_m * 64 + mt * 16 + (lane >> 2);
        const int r1 = r0 + 8;
        size_t q0, q1;
        if (invperm) {
            q0 = (size_t)((r0 & ~(SEQ - 1)) | invperm[r0 & (SEQ - 1)]);
            q1 = (size_t)((r1 & ~(SEQ - 1)) | invperm[r1 & (SEQ - 1)]);
        } else { q0 = (size_t)r0; q1 = (size_t)r1; }

#pragma unroll
        for (int nt = 0; nt < 8; ++nt) {
            const int cl = warp_n * 64 + nt * 8 + (lane & 3) * 2;
            const float b0 = bias_s[cl], b1 = bias_s[cl + 1];
            const float v0 = acc[mt][nt][0] + b0, v1 = acc[mt][nt][1] + b1;
            const float v2 = acc[mt][nt][2] + b0, v3 = acc[mt][nt][3] + b1;
            const size_t g0 = q0 * HDIM + n0 + cl;
            const size_t g1 = q1 * HDIM + n0 + cl;
            if (outF) {
                *(float2*)(outF + g0) = make_float2(v0, v1);
                *(float2*)(outF + g1) = make_float2(v2, v3);
            } else {
                __nv_bfloat16 h0, h1, l0, l1;
                split1(v0, h0, l0); split1(v1, h1, l1);
                *(uint32_t*)(outHi + g0) = (uint32_t)__bfloat16_as_ushort(h0) | ((uint32_t)__bfloat16_as_ushort(h1) << 16);
                *(uint32_t*)(outLo + g0) = (uint32_t)__bfloat16_as_ushort(l0) | ((uint32_t)__bfloat16_as_ushort(l1) << 16);
                split1(v2, h0, l0); split1(v3, h1, l1);
                *(uint32_t*)(outHi + g1) = (uint32_t)__bfloat16_as_ushort(h0) | ((uint32_t)__bfloat16_as_ushort(h1) << 16);
                *(uint32_t*)(outLo + g1) = (uint32_t)__bfloat16_as_ushort(l0) | ((uint32_t)__bfloat16_as_ushort(l1) << 16);
            }
        }
    }
}

// ---------------- host launcher ----------------
typedef CUresult (*EncodeFn)(CUtensorMap*, CUtensorMapDataType, cuuint32_t, void*,
                             const cuuint64_t*, const cuuint64_t*, const cuuint32_t*,
                             const cuuint32_t*, CUtensorMapInterleave, CUtensorMapSwizzle,
                             CUtensorMapL2promotion, CUtensorMapFloatOOBfill);

static void make_map(EncodeFn enc, CUtensorMap* m, void* base, uint64_t rows, uint32_t box_rows) {
    cuuint64_t dims[2]    = {(cuuint64_t)HDIM, (cuuint64_t)rows};
    cuuint64_t strides[1] = {(cuuint64_t)HDIM * 2};
    cuuint32_t box[2]     = {(cuuint32_t)BK, (cuuint32_t)box_rows};
    cuuint32_t es[2]      = {1, 1};
    enc(m, CU_TENSOR_MAP_DATA_TYPE_BFLOAT16, 2, base, dims, strides, box, es,
        CU_TENSOR_MAP_INTERLEAVE_NONE, CU_TENSOR_MAP_SWIZZLE_128B,
        CU_TENSOR_MAP_L2_PROMOTION_L2_128B, CU_TENSOR_MAP_FLOAT_OOB_FILL_NONE);
}

extern "C" void kernel_launch(void* const* d_in, const int* in_sizes, int n_in,
                              void* d_out, int out_size)
{
    const float* x       = (const float*)d_in[0];
    const float* weights = (const float*)d_in[1];
    const float* biases  = (const float*)d_in[2];
    const int*   perms   = (const int*)  d_in[3];
    float*       out     = (float*)d_out;

    __nv_bfloat16 *aHi, *aLo, *wHi, *wLo;
    int* inv;
    cudaGetSymbolAddress((void**)&aHi, g_ahi);
    cudaGetSymbolAddress((void**)&aLo, g_alo);
    cudaGetSymbolAddress((void**)&wHi, g_whi);
    cudaGetSymbolAddress((void**)&wLo, g_wlo);
    cudaGetSymbolAddress((void**)&inv, g_inv);

    EncodeFn enc = nullptr;
    cudaDriverEntryPointQueryResult st;
    cudaGetDriverEntryPointByVersion("cuTensorMapEncodeTiled", (void**)&enc, 12000,
                                     cudaEnableDefault, &st);

    cudaFuncSetAttribute(gemm_layer, cudaFuncAttributeMaxDynamicSharedMemorySize, SMEM_TOTAL);

    // pre-pass: splits + inverse perms
    {
        int n4x = (MTOT * HDIM) / 4;
        split_kernel<<<8192, 256>>>(x, aHi, aLo, n4x);
        int n4w = (NLAYER * HDIM * HDIM) / 4;
        split_kernel<<<8192, 256>>>(weights, wHi, wLo, n4w);
        invperm_kernel<<<((NLAYER - 1) * SEQ + 255) / 256, 256>>>(perms, inv);
    }

    const size_t ABUF = (size_t)MTOT * HDIM;
    const size_t WBUF = (size_t)HDIM * HDIM;
    const dim3 grid(HDIM / BN, MTOT / BM);   // (16, 128)

    for (int l = 0; l < NLAYER; ++l) {
        const int ib = l & 1;
        const int ob = ib ^ 1;
        CUtensorMap mAh, mAl, mBh, mBl;
        make_map(enc, &mAh, aHi + (size_t)ib * ABUF, MTOT, BM);
        make_map(enc, &mAl, aLo + (size_t)ib * ABUF, MTOT, BM);
        make_map(enc, &mBh, wHi + (size_t)l * WBUF, HDIM, BN);
        make_map(enc, &mBl, wLo + (size_t)l * WBUF, HDIM, BN);

        if (l < NLAYER - 1) {
            gemm_layer<<<grid, 256, SMEM_TOTAL>>>(
                mAh, mAl, mBh, mBl, biases + (size_t)l * HDIM,
                inv + (size_t)l * SEQ,
                aHi + (size_t)ob * ABUF, aLo + (size_t)ob * ABUF, nullptr);
        } else {
            gemm_layer<<<grid, 256, SMEM_TOTAL>>>(
                mAh, mAl, mBh, mBl, biases + (size_t)l * HDIM,
                nullptr, nullptr, nullptr, out);
        }
    }
}

// round 9
// speedup vs baseline: 4.9067x; 1.4745x over previous
#include <cuda_runtime.h>
#include <cuda_fp16.h>
#include <cuda.h>
#include <cstdint>

// ---------------- problem constants ----------------
#define HDIM   2048
#define SEQ    4096
#define NBATCH 8
#define MTOT   (NBATCH * SEQ)       // 32768
#define NLAYER 4

// ---------------- GEMM tile config ----------------
#define BM 256
#define BN 128
#define BK 64                        // 64 fp16 = 128 B rows (SW128)
#define KCHUNKS (HDIM / BK)          // 32
#define NSTAGES 3

// smem layout (bytes)
#define OFF_FULL(s)  ((s) * 8)       // 3 mbarriers
#define OFF_BIAS     64              // BN floats = 512 B
#define OFF_STAGE    1024
#define OFF_A        0               // 256*128 B = 32768
#define OFF_BH       32768           // 128*128 B = 16384
#define OFF_BL       49152
#define STAGE_BYTES  65536
#define SMEM_TOTAL   (OFF_STAGE + NSTAGES * STAGE_BYTES)   // 197632

// ---------------- device scratch ----------------
__device__ __align__(1024) __half g_act[2ull * MTOT * HDIM];   // ping-pong fp16 activations
__device__ __align__(1024) __half g_whi[(size_t)NLAYER * HDIM * HDIM];
__device__ __align__(1024) __half g_wlo[(size_t)NLAYER * HDIM * HDIM];
__device__ int g_inv[(NLAYER - 1) * SEQ];

// ---------------- PTX helpers (baseline sm_103 only) ----------------
__device__ __forceinline__ uint32_t smem_u32(const void* p) {
    return (uint32_t)__cvta_generic_to_shared(p);
}

#define MBARRIER_INIT(addr, cnt) \
    asm volatile("mbarrier.init.shared.b64 [%0], %1;" :: "r"(addr), "r"(cnt) : "memory")

#define MBARRIER_EXPECT_TX(addr, bytes) \
    asm volatile("mbarrier.arrive.expect_tx.shared.b64 _, [%0], %1;" :: "r"(addr), "r"(bytes) : "memory")

#define MBARRIER_WAIT_PARITY(mbar_smem_addr, phase_parity) do { \
    uint32_t _mbar = (uint32_t)(mbar_smem_addr); \
    uint32_t _parity = (uint32_t)(phase_parity); \
    uint32_t _done_; \
    asm volatile( \
        "{\n\t.reg .pred p;\n\t" \
        "mbarrier.try_wait.parity.acquire.cta.shared::cta.b64 p, [%1], %2;\n\t" \
        "selp.b32 %0, 1, 0, p;\n\t}" \
        : "=r"(_done_) : "r"(_mbar), "r"(_parity) : "memory"); \
    if (!_done_) { \
        asm volatile( \
            "{\n\t.reg .pred P1;\n\t" \
            "WAIT_LOOP_%=:\n\t" \
            "mbarrier.try_wait.parity.acquire.cta.shared::cta.b64 P1, [%0], %1, 0x989680;\n\t" \
            "@P1 bra.uni WAIT_DONE_%=;\n\t" \
            "bra.uni WAIT_LOOP_%=;\n\t" \
            "WAIT_DONE_%=:\n\t}" \
            :: "r"(_mbar), "r"(_parity) : "memory"); \
    } \
} while (0)

#define TMA_LOAD_2D(dst, map, cx, cy, mbar) \
    asm volatile( \
        "cp.async.bulk.tensor.2d.shared::cta.global.tile.mbarrier::complete_tx::bytes " \
        "[%0], [%1, {%2, %3}], [%4];" \
        :: "r"((uint32_t)(dst)), "l"(map), "r"((int)(cx)), "r"((int)(cy)), "r"((uint32_t)(mbar)) \
        : "memory")

__device__ __forceinline__ void ldsm_x4(uint32_t* r, uint32_t addr) {
    asm volatile("ldmatrix.sync.aligned.m8n8.x4.shared.b16 {%0,%1,%2,%3}, [%4];"
        : "=r"(r[0]), "=r"(r[1]), "=r"(r[2]), "=r"(r[3]) : "r"(addr));
}

// D += A * B  (fp16 in, fp32 acc), m16n8k16
__device__ __forceinline__ void mma16816(float* d, const uint32_t* a, const uint32_t* b) {
    asm volatile("mma.sync.aligned.m16n8k16.row.col.f32.f16.f16.f32 "
        "{%0,%1,%2,%3}, {%4,%5,%6,%7}, {%8,%9}, {%0,%1,%2,%3};"
        : "+f"(d[0]), "+f"(d[1]), "+f"(d[2]), "+f"(d[3])
        : "r"(a[0]), "r"(a[1]), "r"(a[2]), "r"(a[3]), "r"(b[0]), "r"(b[1]));
}

// ---------------- pre-kernels ----------------
// x (fp32) -> fp16 activations
__global__ void convert_x_kernel(const float* __restrict__ in,
                                 __half* __restrict__ out, int n4) {
    int stride = gridDim.x * blockDim.x;
    for (int i = blockIdx.x * blockDim.x + threadIdx.x; i < n4; i += stride) {
        float4 f = ((const float4*)in)[i];
        __half2 p0 = __floats2half2_rn(f.x, f.y);
        __half2 p1 = __floats2half2_rn(f.z, f.w);
        ((uint2*)out)[i] = make_uint2(*(uint32_t*)&p0, *(uint32_t*)&p1);
    }
}

// weights (fp32) -> fp16 hi + fp16 lo (lo = residual; may be fp16 denormal, fine)
__global__ void split_w_kernel(const float* __restrict__ in,
                               __half* __restrict__ hi,
                               __half* __restrict__ lo, int n4) {
    int stride = gridDim.x * blockDim.x;
    for (int i = blockIdx.x * blockDim.x + threadIdx.x; i < n4; i += stride) {
        float4 f = ((const float4*)in)[i];
        __half h0 = __float2half_rn(f.x), h1 = __float2half_rn(f.y);
        __half h2 = __float2half_rn(f.z), h3 = __float2half_rn(f.w);
        __half l0 = __float2half_rn(f.x - __half2float(h0));
        __half l1 = __float2half_rn(f.y - __half2float(h1));
        __half l2 = __float2half_rn(f.z - __half2float(h2));
        __half l3 = __float2half_rn(f.w - __half2float(h3));
        uint32_t ph0 = (uint32_t)__half_as_ushort(h0) | ((uint32_t)__half_as_ushort(h1) << 16);
        uint32_t ph1 = (uint32_t)__half_as_ushort(h2) | ((uint32_t)__half_as_ushort(h3) << 16);
        uint32_t pl0 = (uint32_t)__half_as_ushort(l0) | ((uint32_t)__half_as_ushort(l1) << 16);
        uint32_t pl1 = (uint32_t)__half_as_ushort(l2) | ((uint32_t)__half_as_ushort(l3) << 16);
        ((uint2*)hi)[i] = make_uint2(ph0, ph1);
        ((uint2*)lo)[i] = make_uint2(pl0, pl1);
    }
}

__global__ void invperm_kernel(const int* __restrict__ perms, int* __restrict__ inv) {
    int i = blockIdx.x * blockDim.x + threadIdx.x;
    if (i < (NLAYER - 1) * SEQ) {
        int l = i / SEQ, s = i % SEQ;
        inv[l * SEQ + perms[i]] = s;
    }
}

// ---------------- main GEMM layer kernel ----------------
// C[BM x BN] = A_f16 . (Whi + Wlo)^T  (2-term), +bias, scatter by invperm.
__global__ void __launch_bounds__(256, 1)
gemm_layer(const __grid_constant__ CUtensorMap mapA,
           const __grid_constant__ CUtensorMap mapBh,
           const __grid_constant__ CUtensorMap mapBl,
           const float* __restrict__ bias,
           const int* __restrict__ invperm,
           __half* __restrict__ outA,
           float* __restrict__ outF)
{
    extern __shared__ char smem[];
    const uint32_t sb = smem_u32(smem);
    const int tid  = threadIdx.x;
    const int wid  = tid >> 5;
    const int lane = tid & 31;
    const int warp_m = wid & 3;       // 4 warps along M (64 rows each)
    const int warp_n = wid >> 2;      // 2 warps along N (64 cols each)
    const int m0 = blockIdx.y * BM;
    const int n0 = blockIdx.x * BN;

    float* bias_s = (float*)(smem + OFF_BIAS);
    for (int i = tid; i < BN; i += 256) bias_s[i] = bias[n0 + i];

    if (tid == 0) {
        MBARRIER_INIT(sb + OFF_FULL(0), 1);
        MBARRIER_INIT(sb + OFF_FULL(1), 1);
        MBARRIER_INIT(sb + OFF_FULL(2), 1);
    }
    __syncthreads();

    if (tid == 0) {
#pragma unroll
        for (int c = 0; c < NSTAGES; ++c) {
            MBARRIER_EXPECT_TX(sb + OFF_FULL(c), STAGE_BYTES);
            const uint32_t base = sb + OFF_STAGE + c * STAGE_BYTES;
            const int k0 = c * BK;
            TMA_LOAD_2D(base + OFF_A,  &mapA,  k0, m0, sb + OFF_FULL(c));
            TMA_LOAD_2D(base + OFF_BH, &mapBh, k0, n0, sb + OFF_FULL(c));
            TMA_LOAD_2D(base + OFF_BL, &mapBl, k0, n0, sb + OFF_FULL(c));
        }
    }

    // per-lane ldmatrix geometry (SW128, 128B rows: phys_k = k ^ ((row&7)*16))
    const int rin = lane & 7;
    const int t8  = lane >> 3;                       // 8x8 tile index 0..3
    const int a_row_local = ((t8 & 1) << 3) + rin;   // A: tiles 0/1 rows, 2/3 k+16
    const int a_kadd      = (t8 >> 1) << 4;
    const int b_row_local = ((t8 >> 1) << 3) + rin;  // B: tiles 0/1 k, 2/3 n+8
    const int b_kadd      = (t8 & 1) << 4;
    const uint32_t ksw    = (uint32_t)(rin << 4);

    float acc[4][8][4];
#pragma unroll
    for (int i = 0; i < 4; ++i)
#pragma unroll
        for (int j = 0; j < 8; ++j)
#pragma unroll
            for (int k = 0; k < 4; ++k) acc[i][j][k] = 0.0f;

    for (int c = 0; c < KCHUNKS; ++c) {
        const int st = c % NSTAGES;
        MBARRIER_WAIT_PARITY(sb + OFF_FULL(st), (c / NSTAGES) & 1);
        const uint32_t base = sb + OFF_STAGE + st * STAGE_BYTES;

#pragma unroll
        for (int kk = 0; kk < BK / 16; ++kk) {
            uint32_t af[4][4];
#pragma unroll
            for (int mt = 0; mt < 4; ++mt) {
                const int row = warp_m * 64 + mt * 16 + a_row_local;
                const uint32_t koff = (uint32_t)(kk * 32 + a_kadd) ^ ksw;
                ldsm_x4(af[mt], base + OFF_A + row * 128 + koff);
            }
#pragma unroll
            for (int g = 0; g < 4; ++g) {
                const int rowb = warp_n * 64 + g * 16 + b_row_local;
                const uint32_t koff = (uint32_t)(kk * 32 + b_kadd) ^ ksw;
                const uint32_t baddr = base + OFF_BH + rowb * 128 + koff;
                uint32_t bh[4], bl[4];
                ldsm_x4(bh, baddr);
                ldsm_x4(bl, baddr + (OFF_BL - OFF_BH));
                // hi pass (8 mma), then lo pass (8 mma): same-acc MMAs separated
#pragma unroll
                for (int mt = 0; mt < 4; ++mt) {
                    mma16816(acc[mt][2 * g],     af[mt], bh);
                    mma16816(acc[mt][2 * g + 1], af[mt], bh + 2);
                }
#pragma unroll
                for (int mt = 0; mt < 4; ++mt) {
                    mma16816(acc[mt][2 * g],     af[mt], bl);
                    mma16816(acc[mt][2 * g + 1], af[mt], bl + 2);
                }
            }
        }
        __syncthreads();           // all warps done with stage st before refill
        if (tid == 0 && c + NSTAGES < KCHUNKS) {
            MBARRIER_EXPECT_TX(sb + OFF_FULL(st), STAGE_BYTES);
            const int k0 = (c + NSTAGES) * BK;
            TMA_LOAD_2D(base + OFF_A,  &mapA,  k0, m0, sb + OFF_FULL(st));
            TMA_LOAD_2D(base + OFF_BH, &mapBh, k0, n0, sb + OFF_FULL(st));
            TMA_LOAD_2D(base + OFF_BL, &mapBl, k0, n0, sb + OFF_FULL(st));
        }
    }

    // ---------------- epilogue: bias + (scatter fp16 | fp32 store) ----------------
#pragma unroll
    for (int mt = 0; mt < 4; ++mt) {
        const int r0 = m0 + warp_m * 64 + mt * 16 + (lane >> 2);
        const int r1 = r0 + 8;
        size_t q0, q1;
        if (invperm) {
            q0 = (size_t)((r0 & ~(SEQ - 1)) | invperm[r0 & (SEQ - 1)]);
            q1 = (size_t)((r1 & ~(SEQ - 1)) | invperm[r1 & (SEQ - 1)]);
        } else { q0 = (size_t)r0; q1 = (size_t)r1; }

#pragma unroll
        for (int nt = 0; nt < 8; ++nt) {
            const int cl = warp_n * 64 + nt * 8 + (lane & 3) * 2;
            const float b0 = bias_s[cl], b1 = bias_s[cl + 1];
            const float v0 = acc[mt][nt][0] + b0, v1 = acc[mt][nt][1] + b1;
            const float v2 = acc[mt][nt][2] + b0, v3 = acc[mt][nt][3] + b1;
            const size_t g0 = q0 * HDIM + n0 + cl;
            const size_t g1 = q1 * HDIM + n0 + cl;
            if (outF) {
                *(float2*)(outF + g0) = make_float2(v0, v1);
                *(float2*)(outF + g1) = make_float2(v2, v3);
            } else {
                __half2 p0 = __floats2half2_rn(v0, v1);
                __half2 p1 = __floats2half2_rn(v2, v3);
                *(__half2*)(outA + g0) = p0;
                *(__half2*)(outA + g1) = p1;
            }
        }
    }
}

// ---------------- host launcher ----------------
typedef CUresult (*EncodeFn)(CUtensorMap*, CUtensorMapDataType, cuuint32_t, void*,
                             const cuuint64_t*, const cuuint64_t*, const cuuint32_t*,
                             const cuuint32_t*, CUtensorMapInterleave, CUtensorMapSwizzle,
                             CUtensorMapL2promotion, CUtensorMapFloatOOBfill);

static void make_map(EncodeFn enc, CUtensorMap* m, void* base, uint64_t rows, uint32_t box_rows) {
    cuuint64_t dims[2]    = {(cuuint64_t)HDIM, (cuuint64_t)rows};
    cuuint64_t strides[1] = {(cuuint64_t)HDIM * 2};
    cuuint32_t box[2]     = {(cuuint32_t)BK, (cuuint32_t)box_rows};
    cuuint32_t es[2]      = {1, 1};
    enc(m, CU_TENSOR_MAP_DATA_TYPE_FLOAT16, 2, base, dims, strides, box, es,
        CU_TENSOR_MAP_INTERLEAVE_NONE, CU_TENSOR_MAP_SWIZZLE_128B,
        CU_TENSOR_MAP_L2_PROMOTION_L2_128B, CU_TENSOR_MAP_FLOAT_OOB_FILL_NONE);
}

extern "C" void kernel_launch(void* const* d_in, const int* in_sizes, int n_in,
                              void* d_out, int out_size)
{
    const float* x       = (const float*)d_in[0];
    const float* weights = (const float*)d_in[1];
    const float* biases  = (const float*)d_in[2];
    const int*   perms   = (const int*)  d_in[3];
    float*       out     = (float*)d_out;

    __half *act, *wHi, *wLo;
    int* inv;
    cudaGetSymbolAddress((void**)&act, g_act);
    cudaGetSymbolAddress((void**)&wHi, g_whi);
    cudaGetSymbolAddress((void**)&wLo, g_wlo);
    cudaGetSymbolAddress((void**)&inv, g_inv);

    EncodeFn enc = nullptr;
    cudaDriverEntryPointQueryResult st;
    cudaGetDriverEntryPointByVersion("cuTensorMapEncodeTiled", (void**)&enc, 12000,
                                     cudaEnableDefault, &st);

    cudaFuncSetAttribute(gemm_layer, cudaFuncAttributeMaxDynamicSharedMemorySize, SMEM_TOTAL);

    // pre-pass: x -> fp16, weights -> hi/lo fp16, inverse perms
    {
        int n4x = (MTOT * HDIM) / 4;
        convert_x_kernel<<<8192, 256>>>(x, act, n4x);
        int n4w = (NLAYER * HDIM * HDIM) / 4;
        split_w_kernel<<<8192, 256>>>(weights, wHi, wLo, n4w);
        invperm_kernel<<<((NLAYER - 1) * SEQ + 255) / 256, 256>>>(perms, inv);
    }

    const size_t ABUF = (size_t)MTOT * HDIM;
    const size_t WBUF = (size_t)HDIM * HDIM;
    const dim3 grid(HDIM / BN, MTOT / BM);   // (16, 128)

    for (int l = 0; l < NLAYER; ++l) {
        const int ib = l & 1;
        const int ob = ib ^ 1;
        CUtensorMap mA, mBh, mBl;
        make_map(enc, &mA,  act + (size_t)ib * ABUF, MTOT, BM);
        make_map(enc, &mBh, wHi + (size_t)l * WBUF, HDIM, BN);
        make_map(enc, &mBl, wLo + (size_t)l * WBUF, HDIM, BN);

        if (l < NLAYER - 1) {
            gemm_layer<<<grid, 256, SMEM_TOTAL>>>(
                mA, mBh, mBl, biases + (size_t)l * HDIM,
                inv + (size_t)l * SEQ,
                act + (size_t)ob * ABUF, nullptr);
        } else {
            gemm_layer<<<grid, 256, SMEM_TOTAL>>>(
                mA, mBh, mBl, biases + (size_t)l * HDIM,
                nullptr, nullptr, out);
        }
    }
}

// round 10
// speedup vs baseline: 9.5497x; 1.9463x over previous
#include <cuda_runtime.h>
#include <cuda_fp16.h>
#include <cuda.h>
#include <cstdint>

// ---------------- problem constants ----------------
#define HDIM   2048
#define SEQ    4096
#define NBATCH 8
#define MTOT   (NBATCH * SEQ)       // 32768
#define NLAYER 4

// ---------------- GEMM tile config ----------------
#define BM 256
#define BN 128
#define BK 64                        // 64 fp16 = 128 B rows (SW128)
#define KCHUNKS (HDIM / BK)          // 32
#define NSTAGES 4

// smem layout (bytes)
#define OFF_FULL(s)  ((s) * 8)       // 4 full barriers @ 0..31
#define OFF_EMPTY(s) (32 + (s) * 8)  // 4 empty barriers @ 32..63
#define OFF_BIAS     128             // BN floats = 512 B
#define OFF_STAGE    1024
#define OFF_A        0               // 256*128 B = 32768
#define OFF_B        32768           // 128*128 B = 16384
#define STAGE_BYTES  49152
#define SMEM_TOTAL   (OFF_STAGE + NSTAGES * STAGE_BYTES)   // 197632

// ---------------- device scratch ----------------
__device__ __align__(1024) __half g_act[2ull * MTOT * HDIM];   // ping-pong fp16 activations
__device__ __align__(1024) __half g_w[(size_t)NLAYER * HDIM * HDIM];
__device__ int g_inv[(NLAYER - 1) * SEQ];

// ---------------- PTX helpers (baseline sm_103 only) ----------------
__device__ __forceinline__ uint32_t smem_u32(const void* p) {
    return (uint32_t)__cvta_generic_to_shared(p);
}

#define MBARRIER_INIT(addr, cnt) \
    asm volatile("mbarrier.init.shared.b64 [%0], %1;" :: "r"(addr), "r"(cnt) : "memory")

#define MBARRIER_ARRIVE(addr) \
    asm volatile("mbarrier.arrive.shared.b64 _, [%0];" :: "r"(addr) : "memory")

#define MBARRIER_EXPECT_TX(addr, bytes) \
    asm volatile("mbarrier.arrive.expect_tx.shared.b64 _, [%0], %1;" :: "r"(addr), "r"(bytes) : "memory")

#define MBARRIER_WAIT_PARITY(mbar_smem_addr, phase_parity) do { \
    uint32_t _mbar = (uint32_t)(mbar_smem_addr); \
    uint32_t _parity = (uint32_t)(phase_parity); \
    uint32_t _done_; \
    asm volatile( \
        "{\n\t.reg .pred p;\n\t" \
        "mbarrier.try_wait.parity.acquire.cta.shared::cta.b64 p, [%1], %2;\n\t" \
        "selp.b32 %0, 1, 0, p;\n\t}" \
        : "=r"(_done_) : "r"(_mbar), "r"(_parity) : "memory"); \
    if (!_done_) { \
        asm volatile( \
            "{\n\t.reg .pred P1;\n\t" \
            "WAIT_LOOP_%=:\n\t" \
            "mbarrier.try_wait.parity.acquire.cta.shared::cta.b64 P1, [%0], %1, 0x989680;\n\t" \
            "@P1 bra.uni WAIT_DONE_%=;\n\t" \
            "bra.uni WAIT_LOOP_%=;\n\t" \
            "WAIT_DONE_%=:\n\t}" \
            :: "r"(_mbar), "r"(_parity) : "memory"); \
    } \
} while (0)

#define TMA_LOAD_2D(dst, map, cx, cy, mbar) \
    asm volatile( \
        "cp.async.bulk.tensor.2d.shared::cta.global.tile.mbarrier::complete_tx::bytes " \
        "[%0], [%1, {%2, %3}], [%4];" \
        :: "r"((uint32_t)(dst)), "l"(map), "r"((int)(cx)), "r"((int)(cy)), "r"((uint32_t)(mbar)) \
        : "memory")

__device__ __forceinline__ void ldsm_x4(uint32_t* r, uint32_t addr) {
    asm volatile("ldmatrix.sync.aligned.m8n8.x4.shared.b16 {%0,%1,%2,%3}, [%4];"
        : "=r"(r[0]), "=r"(r[1]), "=r"(r[2]), "=r"(r[3]) : "r"(addr));
}

// D += A * B  (fp16 in, fp32 acc), m16n8k16
__device__ __forceinline__ void mma16816(float* d, const uint32_t* a, const uint32_t* b) {
    asm volatile("mma.sync.aligned.m16n8k16.row.col.f32.f16.f16.f32 "
        "{%0,%1,%2,%3}, {%4,%5,%6,%7}, {%8,%9}, {%0,%1,%2,%3};"
        : "+f"(d[0]), "+f"(d[1]), "+f"(d[2]), "+f"(d[3])
        : "r"(a[0]), "r"(a[1]), "r"(a[2]), "r"(a[3]), "r"(b[0]), "r"(b[1]));
}

// ---------------- pre-kernels ----------------
// fp32 -> fp16 (activations and weights)
__global__ void convert_f16_kernel(const float* __restrict__ in,
                                   __half* __restrict__ out, int n4) {
    int stride = gridDim.x * blockDim.x;
    for (int i = blockIdx.x * blockDim.x + threadIdx.x; i < n4; i += stride) {
        float4 f = ((const float4*)in)[i];
        __half2 p0 = __floats2half2_rn(f.x, f.y);
        __half2 p1 = __floats2half2_rn(f.z, f.w);
        ((uint2*)out)[i] = make_uint2(*(uint32_t*)&p0, *(uint32_t*)&p1);
    }
}

__global__ void invperm_kernel(const int* __restrict__ perms, int* __restrict__ inv) {
    int i = blockIdx.x * blockDim.x + threadIdx.x;
    if (i < (NLAYER - 1) * SEQ) {
        int l = i / SEQ, s = i % SEQ;
        inv[l * SEQ + perms[i]] = s;
    }
}

// ---------------- main GEMM layer kernel ----------------
// C[BM x BN] = A_f16 . W_f16^T, +bias, scatter by invperm.
// Pipeline: 4-stage TMA, full (tx) + empty (8 warp arrivals) mbarriers; no
// per-chunk __syncthreads — warps run ahead independently.
__global__ void __launch_bounds__(256, 1)
gemm_layer(const __grid_constant__ CUtensorMap mapA,
           const __grid_constant__ CUtensorMap mapB,
           const float* __restrict__ bias,
           const int* __restrict__ invperm,
           __half* __restrict__ outA,
           float* __restrict__ outF)
{
    extern __shared__ char smem[];
    const uint32_t sb = smem_u32(smem);
    const int tid  = threadIdx.x;
    const int wid  = tid >> 5;
    const int lane = tid & 31;
    const int warp_m = wid & 3;       // 4 warps along M (64 rows each)
    const int warp_n = wid >> 2;      // 2 warps along N (64 cols each)
    const int m0 = blockIdx.y * BM;
    const int n0 = blockIdx.x * BN;

    float* bias_s = (float*)(smem + OFF_BIAS);
    for (int i = tid; i < BN; i += 256) bias_s[i] = bias[n0 + i];

    if (tid == 0) {
#pragma unroll
        for (int s = 0; s < NSTAGES; ++s) {
            MBARRIER_INIT(sb + OFF_FULL(s), 1);
            MBARRIER_INIT(sb + OFF_EMPTY(s), 8);   // one arrival per warp
        }
    }
    __syncthreads();

    if (tid == 0) {
#pragma unroll
        for (int c = 0; c < NSTAGES; ++c) {
            MBARRIER_EXPECT_TX(sb + OFF_FULL(c), STAGE_BYTES);
            const uint32_t base = sb + OFF_STAGE + c * STAGE_BYTES;
            const int k0 = c * BK;
            TMA_LOAD_2D(base + OFF_A, &mapA, k0, m0, sb + OFF_FULL(c));
            TMA_LOAD_2D(base + OFF_B, &mapB, k0, n0, sb + OFF_FULL(c));
        }
    }

    // per-lane ldmatrix geometry (SW128, 128B rows: phys_k = k ^ ((row&7)*16))
    const int rin = lane & 7;
    const int t8  = lane >> 3;                       // 8x8 tile index 0..3
    const int a_row_local = ((t8 & 1) << 3) + rin;   // A: tiles 0/1 rows, 2/3 k+16
    const int a_kadd      = (t8 >> 1) << 4;
    const int b_row_local = ((t8 >> 1) << 3) + rin;  // B: tiles 0/1 k, 2/3 n+8
    const int b_kadd      = (t8 & 1) << 4;
    const uint32_t ksw    = (uint32_t)(rin << 4);

    float acc[4][8][4];
#pragma unroll
    for (int i = 0; i < 4; ++i)
#pragma unroll
        for (int j = 0; j < 8; ++j)
#pragma unroll
            for (int k = 0; k < 4; ++k) acc[i][j][k] = 0.0f;

    for (int c = 0; c < KCHUNKS; ++c) {
        const int st = c & (NSTAGES - 1);
        const int ph = (c / NSTAGES) & 1;
        MBARRIER_WAIT_PARITY(sb + OFF_FULL(st), ph);
        const uint32_t base = sb + OFF_STAGE + st * STAGE_BYTES;

#pragma unroll
        for (int kk = 0; kk < BK / 16; ++kk) {
            uint32_t af[4][4];
#pragma unroll
            for (int mt = 0; mt < 4; ++mt) {
                const int row = warp_m * 64 + mt * 16 + a_row_local;
                const uint32_t koff = (uint32_t)(kk * 32 + a_kadd) ^ ksw;
                ldsm_x4(af[mt], base + OFF_A + row * 128 + koff);
            }
#pragma unroll
            for (int g = 0; g < 4; ++g) {
                const int rowb = warp_n * 64 + g * 16 + b_row_local;
                const uint32_t koff = (uint32_t)(kk * 32 + b_kadd) ^ ksw;
                uint32_t bf[4];
                ldsm_x4(bf, base + OFF_B + rowb * 128 + koff);
#pragma unroll
                for (int mt = 0; mt < 4; ++mt) {
                    mma16816(acc[mt][2 * g],     af[mt], bf);
                    mma16816(acc[mt][2 * g + 1], af[mt], bf + 2);
                }
            }
        }

        // this warp is done with stage st
        __syncwarp();
        if (lane == 0) MBARRIER_ARRIVE(sb + OFF_EMPTY(st));

        // producer: refill stage st once all 8 warps have drained it
        if (tid == 0 && c + NSTAGES < KCHUNKS) {
            MBARRIER_WAIT_PARITY(sb + OFF_EMPTY(st), ph);
            MBARRIER_EXPECT_TX(sb + OFF_FULL(st), STAGE_BYTES);
            const int k0 = (c + NSTAGES) * BK;
            TMA_LOAD_2D(base + OFF_A, &mapA, k0, m0, sb + OFF_FULL(st));
            TMA_LOAD_2D(base + OFF_B, &mapB, k0, n0, sb + OFF_FULL(st));
        }
    }

    // ---------------- epilogue: bias + (scatter fp16 | fp32 store) ----------------
#pragma unroll
    for (int mt = 0; mt < 4; ++mt) {
        const int r0 = m0 + warp_m * 64 + mt * 16 + (lane >> 2);
        const int r1 = r0 + 8;
        size_t q0, q1;
        if (invperm) {
            q0 = (size_t)((r0 & ~(SEQ - 1)) | invperm[r0 & (SEQ - 1)]);
            q1 = (size_t)((r1 & ~(SEQ - 1)) | invperm[r1 & (SEQ - 1)]);
        } else { q0 = (size_t)r0; q1 = (size_t)r1; }

#pragma unroll
        for (int nt = 0; nt < 8; ++nt) {
            const int cl = warp_n * 64 + nt * 8 + (lane & 3) * 2;
            const float b0 = bias_s[cl], b1 = bias_s[cl + 1];
            const float v0 = acc[mt][nt][0] + b0, v1 = acc[mt][nt][1] + b1;
            const float v2 = acc[mt][nt][2] + b0, v3 = acc[mt][nt][3] + b1;
            const size_t g0 = q0 * HDIM + n0 + cl;
            const size_t g1 = q1 * HDIM + n0 + cl;
            if (outF) {
                *(float2*)(outF + g0) = make_float2(v0, v1);
                *(float2*)(outF + g1) = make_float2(v2, v3);
            } else {
                __half2 p0 = __floats2half2_rn(v0, v1);
                __half2 p1 = __floats2half2_rn(v2, v3);
                *(__half2*)(outA + g0) = p0;
                *(__half2*)(outA + g1) = p1;
            }
        }
    }
}

// ---------------- host launcher ----------------
typedef CUresult (*EncodeFn)(CUtensorMap*, CUtensorMapDataType, cuuint32_t, void*,
                             const cuuint64_t*, const cuuint64_t*, const cuuint32_t*,
                             const cuuint32_t*, CUtensorMapInterleave, CUtensorMapSwizzle,
                             CUtensorMapL2promotion, CUtensorMapFloatOOBfill);

static void make_map(EncodeFn enc, CUtensorMap* m, void* base, uint64_t rows, uint32_t box_rows) {
    cuuint64_t dims[2]    = {(cuuint64_t)HDIM, (cuuint64_t)rows};
    cuuint64_t strides[1] = {(cuuint64_t)HDIM * 2};
    cuuint32_t box[2]     = {(cuuint32_t)BK, (cuuint32_t)box_rows};
    cuuint32_t es[2]      = {1, 1};
    enc(m, CU_TENSOR_MAP_DATA_TYPE_FLOAT16, 2, base, dims, strides, box, es,
        CU_TENSOR_MAP_INTERLEAVE_NONE, CU_TENSOR_MAP_SWIZZLE_128B,
        CU_TENSOR_MAP_L2_PROMOTION_L2_128B, CU_TENSOR_MAP_FLOAT_OOB_FILL_NONE);
}

extern "C" void kernel_launch(void* const* d_in, const int* in_sizes, int n_in,
                              void* d_out, int out_size)
{
    const float* x       = (const float*)d_in[0];
    const float* weights = (const float*)d_in[1];
    const float* biases  = (const float*)d_in[2];
    const int*   perms   = (const int*)  d_in[3];
    float*       out     = (float*)d_out;

    __half *act, *w;
    int* inv;
    cudaGetSymbolAddress((void**)&act, g_act);
    cudaGetSymbolAddress((void**)&w,   g_w);
    cudaGetSymbolAddress((void**)&inv, g_inv);

    EncodeFn enc = nullptr;
    cudaDriverEntryPointQueryResult st;
    cudaGetDriverEntryPointByVersion("cuTensorMapEncodeTiled", (void**)&enc, 12000,
                                     cudaEnableDefault, &st);

    cudaFuncSetAttribute(gemm_layer, cudaFuncAttributeMaxDynamicSharedMemorySize, SMEM_TOTAL);

    // pre-pass: x -> fp16, weights -> fp16, inverse perms
    {
        int n4x = (MTOT * HDIM) / 4;
        convert_f16_kernel<<<8192, 256>>>(x, act, n4x);
        int n4w = (NLAYER * HDIM * HDIM) / 4;
        convert_f16_kernel<<<8192, 256>>>(weights, w, n4w);
        invperm_kernel<<<((NLAYER - 1) * SEQ + 255) / 256, 256>>>(perms, inv);
    }

    const size_t ABUF = (size_t)MTOT * HDIM;
    const size_t WBUF = (size_t)HDIM * HDIM;
    const dim3 grid(HDIM / BN, MTOT / BM);   // (16, 128)

    for (int l = 0; l < NLAYER; ++l) {
        const int ib = l & 1;
        const int ob = ib ^ 1;
        CUtensorMap mA, mB;
        make_map(enc, &mA, act + (size_t)ib * ABUF, MTOT, BM);
        make_map(enc, &mB, w   + (size_t)l * WBUF, HDIM, BN);

        if (l < NLAYER - 1) {
            gemm_layer<<<grid, 256, SMEM_TOTAL>>>(
                mA, mB, biases + (size_t)l * HDIM,
                inv + (size_t)l * SEQ,
                act + (size_t)ob * ABUF, nullptr);
        } else {
            gemm_layer<<<grid, 256, SMEM_TOTAL>>>(
                mA, mB, biases + (size_t)l * HDIM,
                nullptr, nullptr, out);
        }
    }
}

// round 11
// speedup vs baseline: 9.9935x; 1.0465x over previous
#include <cuda_runtime.h>
#include <cuda_fp16.h>
#include <cuda.h>
#include <cstdint>

// ---------------- problem constants ----------------
#define HDIM   2048
#define SEQ    4096
#define NBATCH 8
#define MTOT   (NBATCH * SEQ)       // 32768
#define NLAYER 4

// ---------------- GEMM tile config ----------------
#define BM 128
#define BN 128
#define BK 64                        // 64 fp16 = 128 B rows (SW128)
#define KCHUNKS (HDIM / BK)          // 32
#define NSTAGES 3

// smem layout (bytes)
#define OFF_FULL(s)  ((s) * 8)       // 3 full barriers
#define OFF_EMPTY(s) (32 + (s) * 8)  // 3 empty barriers
#define OFF_BIAS     128             // BN floats = 512 B
#define OFF_STAGE    1024
#define OFF_A        0               // 128*128 B = 16384
#define OFF_B        16384           // 128*128 B = 16384
#define STAGE_BYTES  32768
#define SMEM_TOTAL   (OFF_STAGE + NSTAGES * STAGE_BYTES)   // 99328 -> 2 CTAs/SM

// ---------------- device scratch ----------------
__device__ __align__(1024) __half g_act[2ull * MTOT * HDIM];   // ping-pong fp16 activations
__device__ __align__(1024) __half g_w[(size_t)NLAYER * HDIM * HDIM];
__device__ int g_inv[(NLAYER - 1) * SEQ];

// ---------------- PTX helpers (baseline sm_103 only) ----------------
__device__ __forceinline__ uint32_t smem_u32(const void* p) {
    return (uint32_t)__cvta_generic_to_shared(p);
}

#define MBARRIER_INIT(addr, cnt) \
    asm volatile("mbarrier.init.shared.b64 [%0], %1;" :: "r"(addr), "r"(cnt) : "memory")

#define MBARRIER_ARRIVE(addr) \
    asm volatile("mbarrier.arrive.shared.b64 _, [%0];" :: "r"(addr) : "memory")

#define MBARRIER_EXPECT_TX(addr, bytes) \
    asm volatile("mbarrier.arrive.expect_tx.shared.b64 _, [%0], %1;" :: "r"(addr), "r"(bytes) : "memory")

#define MBARRIER_WAIT_PARITY(mbar_smem_addr, phase_parity) do { \
    uint32_t _mbar = (uint32_t)(mbar_smem_addr); \
    uint32_t _parity = (uint32_t)(phase_parity); \
    uint32_t _done_; \
    asm volatile( \
        "{\n\t.reg .pred p;\n\t" \
        "mbarrier.try_wait.parity.acquire.cta.shared::cta.b64 p, [%1], %2;\n\t" \
        "selp.b32 %0, 1, 0, p;\n\t}" \
        : "=r"(_done_) : "r"(_mbar), "r"(_parity) : "memory"); \
    if (!_done_) { \
        asm volatile( \
            "{\n\t.reg .pred P1;\n\t" \
            "WAIT_LOOP_%=:\n\t" \
            "mbarrier.try_wait.parity.acquire.cta.shared::cta.b64 P1, [%0], %1, 0x989680;\n\t" \
            "@P1 bra.uni WAIT_DONE_%=;\n\t" \
            "bra.uni WAIT_LOOP_%=;\n\t" \
            "WAIT_DONE_%=:\n\t}" \
            :: "r"(_mbar), "r"(_parity) : "memory"); \
    } \
} while (0)

#define TMA_LOAD_2D(dst, map, cx, cy, mbar) \
    asm volatile( \
        "cp.async.bulk.tensor.2d.shared::cta.global.tile.mbarrier::complete_tx::bytes " \
        "[%0], [%1, {%2, %3}], [%4];" \
        :: "r"((uint32_t)(dst)), "l"(map), "r"((int)(cx)), "r"((int)(cy)), "r"((uint32_t)(mbar)) \
        : "memory")

__device__ __forceinline__ void ldsm_x4(uint32_t* r, uint32_t addr) {
    asm volatile("ldmatrix.sync.aligned.m8n8.x4.shared.b16 {%0,%1,%2,%3}, [%4];"
        : "=r"(r[0]), "=r"(r[1]), "=r"(r[2]), "=r"(r[3]) : "r"(addr));
}

// D += A * B  (fp16 in, fp32 acc), m16n8k16
__device__ __forceinline__ void mma16816(float* d, const uint32_t* a, const uint32_t* b) {
    asm volatile("mma.sync.aligned.m16n8k16.row.col.f32.f16.f16.f32 "
        "{%0,%1,%2,%3}, {%4,%5,%6,%7}, {%8,%9}, {%0,%1,%2,%3};"
        : "+f"(d[0]), "+f"(d[1]), "+f"(d[2]), "+f"(d[3])
        : "r"(a[0]), "r"(a[1]), "r"(a[2]), "r"(a[3]), "r"(b[0]), "r"(b[1]));
}

// ---------------- pre-kernels ----------------
__global__ void convert_f16_kernel(const float* __restrict__ in,
                                   __half* __restrict__ out, int n4) {
    int stride = gridDim.x * blockDim.x;
    for (int i = blockIdx.x * blockDim.x + threadIdx.x; i < n4; i += stride) {
        float4 f = ((const float4*)in)[i];
        __half2 p0 = __floats2half2_rn(f.x, f.y);
        __half2 p1 = __floats2half2_rn(f.z, f.w);
        ((uint2*)out)[i] = make_uint2(*(uint32_t*)&p0, *(uint32_t*)&p1);
    }
}

__global__ void invperm_kernel(const int* __restrict__ perms, int* __restrict__ inv) {
    int i = blockIdx.x * blockDim.x + threadIdx.x;
    if (i < (NLAYER - 1) * SEQ) {
        int l = i / SEQ, s = i % SEQ;
        inv[l * SEQ + perms[i]] = s;
    }
}

// ---------------- main GEMM layer kernel ----------------
// C[BM x BN] = A_f16 . W_f16^T, +bias, scatter by invperm.
// 3-stage TMA pipeline; full(tx)+empty(8 warp arrivals) mbarriers; 2 CTAs/SM
// so prologue/epilogue/bubbles of one CTA overlap the other's MMA stream.
__global__ void __launch_bounds__(256, 2)
gemm_layer(const __grid_constant__ CUtensorMap mapA,
           const __grid_constant__ CUtensorMap mapB,
           const float* __restrict__ bias,
           const int* __restrict__ invperm,
           __half* __restrict__ outA,
           float* __restrict__ outF)
{
    extern __shared__ char smem[];
    const uint32_t sb = smem_u32(smem);
    const int tid  = threadIdx.x;
    const int wid  = tid >> 5;
    const int lane = tid & 31;
    const int warp_m = wid & 3;       // 4 warps along M (32 rows each)
    const int warp_n = wid >> 2;      // 2 warps along N (64 cols each)
    const int m0 = blockIdx.y * BM;
    const int n0 = blockIdx.x * BN;

    float* bias_s = (float*)(smem + OFF_BIAS);
    for (int i = tid; i < BN; i += 256) bias_s[i] = bias[n0 + i];

    if (tid == 0) {
#pragma unroll
        for (int s = 0; s < NSTAGES; ++s) {
            MBARRIER_INIT(sb + OFF_FULL(s), 1);
            MBARRIER_INIT(sb + OFF_EMPTY(s), 8);   // one arrival per warp
        }
    }
    __syncthreads();

    if (tid == 0) {
#pragma unroll
        for (int c = 0; c < NSTAGES; ++c) {
            MBARRIER_EXPECT_TX(sb + OFF_FULL(c), STAGE_BYTES);
            const uint32_t base = sb + OFF_STAGE + c * STAGE_BYTES;
            const int k0 = c * BK;
            TMA_LOAD_2D(base + OFF_A, &mapA, k0, m0, sb + OFF_FULL(c));
            TMA_LOAD_2D(base + OFF_B, &mapB, k0, n0, sb + OFF_FULL(c));
        }
    }

    // per-lane ldmatrix geometry (SW128, 128B rows: phys_k = k ^ ((row&7)*16))
    const int rin = lane & 7;
    const int t8  = lane >> 3;                       // 8x8 tile index 0..3
    const int a_row_local = ((t8 & 1) << 3) + rin;   // A: tiles 0/1 rows, 2/3 k+16
    const int a_kadd      = (t8 >> 1) << 4;
    const int b_row_local = ((t8 >> 1) << 3) + rin;  // B: tiles 0/1 k, 2/3 n+8
    const int b_kadd      = (t8 & 1) << 4;
    const uint32_t ksw    = (uint32_t)(rin << 4);

    float acc[2][8][4];
#pragma unroll
    for (int i = 0; i < 2; ++i)
#pragma unroll
        for (int j = 0; j < 8; ++j)
#pragma unroll
            for (int k = 0; k < 4; ++k) acc[i][j][k] = 0.0f;

    int st = 0, ph = 0;
    for (int c = 0; c < KCHUNKS; ++c) {
        MBARRIER_WAIT_PARITY(sb + OFF_FULL(st), ph);
        const uint32_t base = sb + OFF_STAGE + st * STAGE_BYTES;

#pragma unroll
        for (int kk = 0; kk < BK / 16; ++kk) {
            uint32_t af[2][4];
#pragma unroll
            for (int mt = 0; mt < 2; ++mt) {
                const int row = warp_m * 32 + mt * 16 + a_row_local;
                const uint32_t koff = (uint32_t)(kk * 32 + a_kadd) ^ ksw;
                ldsm_x4(af[mt], base + OFF_A + row * 128 + koff);
            }
#pragma unroll
            for (int g = 0; g < 4; ++g) {
                const int rowb = warp_n * 64 + g * 16 + b_row_local;
                const uint32_t koff = (uint32_t)(kk * 32 + b_kadd) ^ ksw;
                uint32_t bf[4];
                ldsm_x4(bf, base + OFF_B + rowb * 128 + koff);
#pragma unroll
                for (int mt = 0; mt < 2; ++mt) {
                    mma16816(acc[mt][2 * g],     af[mt], bf);
                    mma16816(acc[mt][2 * g + 1], af[mt], bf + 2);
                }
            }
        }

        // this warp is done with stage st
        __syncwarp();
        if (lane == 0) MBARRIER_ARRIVE(sb + OFF_EMPTY(st));

        // producer: refill stage st once all 8 warps have drained it
        if (tid == 0 && c + NSTAGES < KCHUNKS) {
            MBARRIER_WAIT_PARITY(sb + OFF_EMPTY(st), ph);
            MBARRIER_EXPECT_TX(sb + OFF_FULL(st), STAGE_BYTES);
            const int k0 = (c + NSTAGES) * BK;
            TMA_LOAD_2D(base + OFF_A, &mapA, k0, m0, sb + OFF_FULL(st));
            TMA_LOAD_2D(base + OFF_B, &mapB, k0, n0, sb + OFF_FULL(st));
        }

        if (++st == NSTAGES) { st = 0; ph ^= 1; }
    }

    // ---------------- epilogue: bias + (scatter fp16 | fp32 store) ----------------
#pragma unroll
    for (int mt = 0; mt < 2; ++mt) {
        const int r0 = m0 + warp_m * 32 + mt * 16 + (lane >> 2);
        const int r1 = r0 + 8;
        size_t q0, q1;
        if (invperm) {
            q0 = (size_t)((r0 & ~(SEQ - 1)) | invperm[r0 & (SEQ - 1)]);
            q1 = (size_t)((r1 & ~(SEQ - 1)) | invperm[r1 & (SEQ - 1)]);
        } else { q0 = (size_t)r0; q1 = (size_t)r1; }

#pragma unroll
        for (int nt = 0; nt < 8; ++nt) {
            const int cl = warp_n * 64 + nt * 8 + (lane & 3) * 2;
            const float b0 = bias_s[cl], b1 = bias_s[cl + 1];
            const float v0 = acc[mt][nt][0] + b0, v1 = acc[mt][nt][1] + b1;
            const float v2 = acc[mt][nt][2] + b0, v3 = acc[mt][nt][3] + b1;
            const size_t g0 = q0 * HDIM + n0 + cl;
            const size_t g1 = q1 * HDIM + n0 + cl;
            if (outF) {
                *(float2*)(outF + g0) = make_float2(v0, v1);
                *(float2*)(outF + g1) = make_float2(v2, v3);
            } else {
                __half2 p0 = __floats2half2_rn(v0, v1);
                __half2 p1 = __floats2half2_rn(v2, v3);
                *(__half2*)(outA + g0) = p0;
                *(__half2*)(outA + g1) = p1;
            }
        }
    }
}

// ---------------- host launcher ----------------
typedef CUresult (*EncodeFn)(CUtensorMap*, CUtensorMapDataType, cuuint32_t, void*,
                             const cuuint64_t*, const cuuint64_t*, const cuuint32_t*,
                             const cuuint32_t*, CUtensorMapInterleave, CUtensorMapSwizzle,
                             CUtensorMapL2promotion, CUtensorMapFloatOOBfill);

static void make_map(EncodeFn enc, CUtensorMap* m, void* base, uint64_t rows, uint32_t box_rows) {
    cuuint64_t dims[2]    = {(cuuint64_t)HDIM, (cuuint64_t)rows};
    cuuint64_t strides[1] = {(cuuint64_t)HDIM * 2};
    cuuint32_t box[2]     = {(cuuint32_t)BK, (cuuint32_t)box_rows};
    cuuint32_t es[2]      = {1, 1};
    enc(m, CU_TENSOR_MAP_DATA_TYPE_FLOAT16, 2, base, dims, strides, box, es,
        CU_TENSOR_MAP_INTERLEAVE_NONE, CU_TENSOR_MAP_SWIZZLE_128B,
        CU_TENSOR_MAP_L2_PROMOTION_L2_128B, CU_TENSOR_MAP_FLOAT_OOB_FILL_NONE);
}

extern "C" void kernel_launch(void* const* d_in, const int* in_sizes, int n_in,
                              void* d_out, int out_size)
{
    const float* x       = (const float*)d_in[0];
    const float* weights = (const float*)d_in[1];
    const float* biases  = (const float*)d_in[2];
    const int*   perms   = (const int*)  d_in[3];
    float*       out     = (float*)d_out;

    __half *act, *w;
    int* inv;
    cudaGetSymbolAddress((void**)&act, g_act);
    cudaGetSymbolAddress((void**)&w,   g_w);
    cudaGetSymbolAddress((void**)&inv, g_inv);

    EncodeFn enc = nullptr;
    cudaDriverEntryPointQueryResult st;
    cudaGetDriverEntryPointByVersion("cuTensorMapEncodeTiled", (void**)&enc, 12000,
                                     cudaEnableDefault, &st);

    cudaFuncSetAttribute(gemm_layer, cudaFuncAttributeMaxDynamicSharedMemorySize, SMEM_TOTAL);

    // pre-pass: x -> fp16, weights -> fp16, inverse perms
    {
        int n4x = (MTOT * HDIM) / 4;
        convert_f16_kernel<<<8192, 256>>>(x, act, n4x);
        int n4w = (NLAYER * HDIM * HDIM) / 4;
        convert_f16_kernel<<<8192, 256>>>(weights, w, n4w);
        invperm_kernel<<<((NLAYER - 1) * SEQ + 255) / 256, 256>>>(perms, inv);
    }

    const size_t ABUF = (size_t)MTOT * HDIM;
    const size_t WBUF = (size_t)HDIM * HDIM;
    const dim3 grid(HDIM / BN, MTOT / BM);   // (16, 256)

    for (int l = 0; l < NLAYER; ++l) {
        const int ib = l & 1;
        const int ob = ib ^ 1;
        CUtensorMap mA, mB;
        make_map(enc, &mA, act + (size_t)ib * ABUF, MTOT, BM);
        make_map(enc, &mB, w   + (size_t)l * WBUF, HDIM, BN);

        if (l < NLAYER - 1) {
            gemm_layer<<<grid, 256, SMEM_TOTAL>>>(
                mA, mB, biases + (size_t)l * HDIM,
                inv + (size_t)l * SEQ,
                act + (size_t)ob * ABUF, nullptr);
        } else {
            gemm_layer<<<grid, 256, SMEM_TOTAL>>>(
                mA, mB, biases + (size_t)l * HDIM,
                nullptr, nullptr, out);
        }
    }
}